// round 16
// baseline (speedup 1.0000x reference)
#include <cuda_runtime.h>
#include <cuda_fp16.h>
#include <cstdint>

// Problem constants
#define TSEQ   2048
#define DMODEL 2048
#define NHEADS 16
#define DHEAD  128
#define BATCH  2
#define BROWS  (BATCH * TSEQ)      // 4096
#define QKVW   (3 * DMODEL)        // 6144
#define NBH    (BATCH * NHEADS)    // 32

typedef __half fp16;

// ---------------------------------------------------------------------------
// Scratch
// ---------------------------------------------------------------------------
__device__ fp16  g_xn_hi [(long long)BROWS * DMODEL];
__device__ fp16  g_wqkv_h[(long long)QKVW * DMODEL];
__device__ fp16  g_wout_h[(long long)DMODEL * DMODEL];
__device__ fp16  g_qkv_hi[(long long)BROWS * QKVW];
__device__ fp16  g_y_hi  [(long long)BROWS * DMODEL];

// ---------------------------------------------------------------------------
// helpers
// ---------------------------------------------------------------------------
__device__ __forceinline__ uint32_t pack2h(fp16 a, fp16 b) {
    __half2 p = __halves2half2(a, b);
    return *(uint32_t*)&p;
}
__device__ __forceinline__ float warpSum(float v) {
#pragma unroll
    for (int o = 16; o; o >>= 1) v += __shfl_xor_sync(0xffffffffu, v, o);
    return v;
}

// ---------------------------------------------------------------------------
// RMSNorm -> fp16
// ---------------------------------------------------------------------------
__global__ __launch_bounds__(256) void rmsnorm_kernel(
    const float* __restrict__ x, const float* __restrict__ w,
    fp16* __restrict__ xh)
{
    long long base = (long long)blockIdx.x * DMODEL;
    int tid = threadIdx.x;
    const float4* xr = (const float4*)(x + base);
    float4 v0 = xr[tid];
    float4 v1 = xr[tid + 256];
    float s = v0.x*v0.x + v0.y*v0.y + v0.z*v0.z + v0.w*v0.w
            + v1.x*v1.x + v1.y*v1.y + v1.z*v1.z + v1.w*v1.w;

    __shared__ float sh[8];
    s = warpSum(s);
    if ((tid & 31) == 0) sh[tid >> 5] = s;
    __syncthreads();
    float tot = 0.f;
#pragma unroll
    for (int i = 0; i < 8; i++) tot += sh[i];
    float r = rsqrtf(tot / (float)DMODEL + 1e-6f);

    const float4* wr = (const float4*)w;
    float4 w0 = wr[tid], w1 = wr[tid + 256];
    float4 o0, o1;
    o0.x = v0.x*r*w0.x; o0.y = v0.y*r*w0.y; o0.z = v0.z*r*w0.z; o0.w = v0.w*r*w0.w;
    o1.x = v1.x*r*w1.x; o1.y = v1.y*r*w1.y; o1.z = v1.z*r*w1.z; o1.w = v1.w*r*w1.w;
    fp16* d0 = xh + base + tid*4;
    *(__half2*)(d0)     = __halves2half2(__float2half(o0.x), __float2half(o0.y));
    *(__half2*)(d0 + 2) = __halves2half2(__float2half(o0.z), __float2half(o0.w));
    fp16* d1 = xh + base + 1024 + tid*4;
    *(__half2*)(d1)     = __halves2half2(__float2half(o1.x), __float2half(o1.y));
    *(__half2*)(d1 + 2) = __halves2half2(__float2half(o1.z), __float2half(o1.w));
}

// ---------------------------------------------------------------------------
// fp32 -> fp16 conversion for BOTH weight matrices in one launch.
// n4a covers wqkv (first region), remainder covers wout.
// ---------------------------------------------------------------------------
__global__ __launch_bounds__(256) void convert_both(
    const float* __restrict__ srcA, fp16* __restrict__ dstA, int n4a,
    const float* __restrict__ srcB, fp16* __restrict__ dstB, int n4total)
{
    int i = blockIdx.x * 256 + threadIdx.x;
    if (i < n4total) {
        const float* s; fp16* d; int k;
        if (i < n4a) { s = srcA; d = dstA; k = i; }
        else         { s = srcB; d = dstB; k = i - n4a; }
        float4 v = ((const float4*)s)[k];
        fp16* o = d + (long long)k*4;
        *(__half2*)(o)     = __halves2half2(__float2half(v.x), __float2half(v.y));
        *(__half2*)(o + 2) = __halves2half2(__float2half(v.z), __float2half(v.w));
    }
}

// ---------------------------------------------------------------------------
// mma.sync primitives (fp16)
// ---------------------------------------------------------------------------
__device__ __forceinline__ void ldsm_x4(uint32_t& r0, uint32_t& r1, uint32_t& r2, uint32_t& r3, uint32_t addr) {
    asm volatile("ldmatrix.sync.aligned.m8n8.x4.shared.b16 {%0,%1,%2,%3}, [%4];"
        : "=r"(r0), "=r"(r1), "=r"(r2), "=r"(r3) : "r"(addr));
}
__device__ __forceinline__ void ldsm_x4_t(uint32_t& r0, uint32_t& r1, uint32_t& r2, uint32_t& r3, uint32_t addr) {
    asm volatile("ldmatrix.sync.aligned.m8n8.x4.trans.shared.b16 {%0,%1,%2,%3}, [%4];"
        : "=r"(r0), "=r"(r1), "=r"(r2), "=r"(r3) : "r"(addr));
}
__device__ __forceinline__ void mma16816(float* d, uint32_t a0, uint32_t a1, uint32_t a2, uint32_t a3,
                                         uint32_t b0, uint32_t b1) {
    asm volatile("mma.sync.aligned.m16n8k16.row.col.f32.f16.f16.f32 "
        "{%0,%1,%2,%3}, {%4,%5,%6,%7}, {%8,%9}, {%0,%1,%2,%3};"
        : "+f"(d[0]), "+f"(d[1]), "+f"(d[2]), "+f"(d[3])
        : "r"(a0), "r"(a1), "r"(a2), "r"(a3), "r"(b0), "r"(b1));
}
__device__ __forceinline__ void cp16(uint32_t dst, const void* src) {
    asm volatile("cp.async.cg.shared.global [%0], [%1], 16;" :: "r"(dst), "l"(src));
}
__device__ __forceinline__ void cp_commit() {
    asm volatile("cp.async.commit_group;" ::: "memory");
}
template<int N>
__device__ __forceinline__ void cp_wait() {
    asm volatile("cp.async.wait_group %0;" :: "n"(N) : "memory");
}
__device__ __forceinline__ uint32_t smem_u32(const void* p) {
    uint32_t a;
    asm("{ .reg .u64 t; cvta.to.shared.u64 t, %1; cvt.u32.u64 %0, t; }" : "=r"(a) : "l"(p));
    return a;
}
// swizzled addr inside a [rows x 128 halves] tile (256B rows, 16 x 16B chunks)
__device__ __forceinline__ uint32_t swz256(int row, int ch) {
    return (uint32_t)(row * 256 + ((ch ^ (row & 7)) * 16));
}
// swizzled addr inside a [rows x 64 halves] tile (128B rows, 8 x 16B chunks)
__device__ __forceinline__ uint32_t sw_off(int row, int c16) {
    return (uint32_t)(row * 128 + ((c16 ^ (row & 7)) * 16));
}

// ---------------------------------------------------------------------------
// Plain fp16 GEMM, narrow tile for 3-CTA/SM occupancy. (R13, unchanged)
// C[M,N] = A[M,K] * B[N,K]^T. CTA tile 128x64, BK=64, 256 threads,
// 8 warps as 4x2 grid (warp tile 32x32).
// ---------------------------------------------------------------------------
template<bool EPI_HALF>
__global__ __launch_bounds__(256, 3) void gemm_mma(
    const fp16* __restrict__ Ahi, int lda,
    const fp16* __restrict__ Bh, int ldb,
    float* __restrict__ Cf, fp16* __restrict__ Chi, int ldc,
    int K)
{
    const int STAGE = 24576;          // A 16KB + B 8KB
    const int OFF_B = 16384;
    int bm = blockIdx.y, bn = blockIdx.x;

    extern __shared__ char smem[];
    uint32_t sbase = smem_u32(smem);

    int tid = threadIdx.x;
    int wid = tid >> 5, lane = tid & 31;
    int wm = wid >> 1, wn = wid & 1;   // 4 x 2 warp grid: 32 rows x 32 cols per warp

    const fp16* Abase = Ahi + (long long)bm * 128 * lda;
    const fp16* Bbase = Bh  + (long long)bn * 64 * ldb;

    int nIter = K >> 6;

    int lrow = tid >> 3;          // 0..31
    int lseg = tid & 7;           // 16B chunk within 128B row

    auto load_chunk = [&](int kc, int bufsel) {
        int k0 = kc << 6;
        uint32_t st = sbase + bufsel * STAGE;
#pragma unroll
        for (int i = 0; i < 4; i++) {
            int row = lrow + 32 * i;
            cp16(st + sw_off(row, lseg), Abase + (long long)row * lda + k0 + lseg * 8);
        }
#pragma unroll
        for (int i = 0; i < 2; i++) {
            int row = lrow + 32 * i;
            cp16(st + OFF_B + sw_off(row, lseg), Bbase + (long long)row * ldb + k0 + lseg * 8);
        }
        cp_commit();
    };

    float acc[2][4][4];
#pragma unroll
    for (int a = 0; a < 2; a++)
#pragma unroll
        for (int b = 0; b < 4; b++)
#pragma unroll
            for (int c = 0; c < 4; c++) acc[a][b][c] = 0.f;

    int lr8  = (lane & 7) + ((lane >> 3) & 1) * 8;
    int lk16 = (lane >> 4);

    load_chunk(0, 0);

    for (int it = 0; it < nIter; ++it) {
        if (it + 1 < nIter) {
            load_chunk(it + 1, (it + 1) & 1);
            cp_wait<1>();
        } else {
            cp_wait<0>();
        }
        __syncthreads();

        uint32_t As  = sbase + (it & 1) * STAGE;
        uint32_t Bs  = As + OFF_B;
#pragma unroll
        for (int ks = 0; ks < 4; ks++) {
            int c16 = ks * 2 + lk16;
            uint32_t bfr[2][4];
#pragma unroll
            for (int ni = 0; ni < 2; ni++) {
                int row = wn * 32 + ni * 16 + lr8;
                ldsm_x4(bfr[ni][0], bfr[ni][1], bfr[ni][2], bfr[ni][3], Bs + sw_off(row, c16));
            }
            uint32_t ah[2][4];
#pragma unroll
            for (int mi = 0; mi < 2; mi++) {
                int row = wm * 32 + mi * 16 + lr8;
                ldsm_x4(ah[mi][0], ah[mi][1], ah[mi][2], ah[mi][3], As + sw_off(row, c16));
            }
#pragma unroll
            for (int mi = 0; mi < 2; mi++) {
#pragma unroll
                for (int ni = 0; ni < 2; ni++) {
                    mma16816(acc[mi][ni*2+0], ah[mi][0], ah[mi][1], ah[mi][2], ah[mi][3],
                             bfr[ni][0], bfr[ni][2]);
                    mma16816(acc[mi][ni*2+1], ah[mi][0], ah[mi][1], ah[mi][2], ah[mi][3],
                             bfr[ni][1], bfr[ni][3]);
                }
            }
        }
        __syncthreads();
    }

    int g = lane >> 2, t = lane & 3;
    long long Cbase = (long long)bm * 128 * ldc + (long long)bn * 64;
#pragma unroll
    for (int mi = 0; mi < 2; mi++) {
#pragma unroll
        for (int nc = 0; nc < 4; nc++) {
            int m0 = wm * 32 + mi * 16 + g;
            int n0 = wn * 32 + nc * 8 + t * 2;
            float v0 = acc[mi][nc][0];
            float v1 = acc[mi][nc][1];
            float v2 = acc[mi][nc][2];
            float v3 = acc[mi][nc][3];
            if (EPI_HALF) {
                *(__half2*)(Chi + Cbase + (long long)m0*ldc + n0) =
                    __halves2half2(__float2half(v0), __float2half(v1));
                *(__half2*)(Chi + Cbase + (long long)(m0+8)*ldc + n0) =
                    __halves2half2(__float2half(v2), __float2half(v3));
            } else {
                *(float2*)(Cf + Cbase + (long long)m0*ldc + n0)     = make_float2(v0, v1);
                *(float2*)(Cf + Cbase + (long long)(m0+8)*ldc + n0) = make_float2(v2, v3);
            }
        }
    }
}

// ---------------------------------------------------------------------------
// Fused flash attention (causal), plain fp16. (R12-proven 256-thread version)
// smem: Q,K,V = 96KB. 128 q-rows per CTA, 8 warps x 16 rows.
// ---------------------------------------------------------------------------
__global__ __launch_bounds__(256, 1) void flash_attn(
    const fp16* __restrict__ qkvh, fp16* __restrict__ yh)
{
    extern __shared__ char smem[];
    uint32_t sb = smem_u32(smem);
    const uint32_t Qhs = sb;
    const uint32_t Khs = sb + 32768;
    const uint32_t Vhs = sb + 65536;

    int tid = threadIdx.x, lane = tid & 31, wid = tid >> 5;
    int qb = (int)(gridDim.x - 1) - (int)blockIdx.x;
    int z = blockIdx.y; int b = z >> 4, h = z & 15;
    long long rowQ0 = (long long)b * TSEQ + (long long)qb * 128;
    long long rowKV = (long long)b * TSEQ;
    int colQ = h * DHEAD, colK = DMODEL + h * DHEAD, colV = 2*DMODEL + h * DHEAD;

    auto load_tile = [&](uint32_t dst, const fp16* gp, long long grow0, int col0) {
#pragma unroll
        for (int i = 0; i < 8; i++) {
            int lin = tid + 256 * i;
            int row = lin >> 4, ch = lin & 15;
            cp16(dst + swz256(row, ch), gp + (grow0 + row) * QKVW + col0 + ch * 8);
        }
    };

    load_tile(Qhs, qkvh, rowQ0, colQ);
    load_tile(Khs, qkvh, rowKV, colK);
    cp_commit();
    load_tile(Vhs, qkvh, rowKV, colV);
    cp_commit();

    float sacc[16][4];
    float oacc[16][4];
#pragma unroll
    for (int i=0;i<16;i++) { oacc[i][0]=0.f; oacc[i][1]=0.f; oacc[i][2]=0.f; oacc[i][3]=0.f; }
    float m0 = -1e30f, m1 = -1e30f, l0 = 0.f, l1 = 0.f;

    int g = lane >> 2, t = lane & 3;
    int wr = wid * 16;
    int lr8  = (lane & 7) + ((lane >> 3) & 1) * 8;
    int lk16 = lane >> 4;
    int vr8  = (lane & 7) + ((lane >> 4) & 1) * 8;
    int vc   = (lane >> 3) & 1;

    const float sm_scale = 0.08838834764831845f;
    int q0row = qb * 128 + wr + g;
    int q1row = q0row + 8;

    for (int j = 0; j <= qb; ++j) {
        cp_wait<1>();
        __syncthreads();

#pragma unroll
        for (int i=0;i<16;i++) { sacc[i][0]=0.f; sacc[i][1]=0.f; sacc[i][2]=0.f; sacc[i][3]=0.f; }
#pragma unroll
        for (int c = 0; c < 8; c++) {
            int ch = 2*c + lk16;
            int arow = wr + lr8;
            uint32_t ah0,ah1,ah2,ah3;
            ldsm_x4(ah0,ah1,ah2,ah3, Qhs + swz256(arow, ch));
#pragma unroll
            for (int nn = 0; nn < 8; nn++) {
                uint32_t r0,r1,r2,r3;
                ldsm_x4(r0,r1,r2,r3, Khs + swz256(nn*16 + lr8, ch));
                mma16816(sacc[2*nn],   ah0,ah1,ah2,ah3, r0, r2);
                mma16816(sacc[2*nn+1], ah0,ah1,ah2,ah3, r1, r3);
            }
        }

        float nm0 = -1e30f, nm1 = -1e30f;
        bool diag = (j == qb);
#pragma unroll
        for (int i = 0; i < 16; i++) {
            int kc = j*128 + i*8 + 2*t;
            float s0 = sacc[i][0]*sm_scale, s1 = sacc[i][1]*sm_scale;
            float s2 = sacc[i][2]*sm_scale, s3 = sacc[i][3]*sm_scale;
            if (diag) {
                if (kc     > q0row) s0 = -1e30f;
                if (kc + 1 > q0row) s1 = -1e30f;
                if (kc     > q1row) s2 = -1e30f;
                if (kc + 1 > q1row) s3 = -1e30f;
            }
            sacc[i][0]=s0; sacc[i][1]=s1; sacc[i][2]=s2; sacc[i][3]=s3;
            nm0 = fmaxf(nm0, fmaxf(s0, s1));
            nm1 = fmaxf(nm1, fmaxf(s2, s3));
        }
        nm0 = fmaxf(nm0, __shfl_xor_sync(0xffffffffu, nm0, 1));
        nm0 = fmaxf(nm0, __shfl_xor_sync(0xffffffffu, nm0, 2));
        nm1 = fmaxf(nm1, __shfl_xor_sync(0xffffffffu, nm1, 1));
        nm1 = fmaxf(nm1, __shfl_xor_sync(0xffffffffu, nm1, 2));
        nm0 = fmaxf(m0, nm0); nm1 = fmaxf(m1, nm1);
        float al0 = __expf(m0 - nm0), al1 = __expf(m1 - nm1);
        m0 = nm0; m1 = nm1;

        float rs0 = 0.f, rs1 = 0.f;
#pragma unroll
        for (int i = 0; i < 16; i++) {
            float e0 = __expf(sacc[i][0] - nm0);
            float e1 = __expf(sacc[i][1] - nm0);
            float e2 = __expf(sacc[i][2] - nm1);
            float e3 = __expf(sacc[i][3] - nm1);
            rs0 += e0 + e1; rs1 += e2 + e3;
            sacc[i][0]=e0; sacc[i][1]=e1; sacc[i][2]=e2; sacc[i][3]=e3;
        }
        rs0 += __shfl_xor_sync(0xffffffffu, rs0, 1);
        rs0 += __shfl_xor_sync(0xffffffffu, rs0, 2);
        rs1 += __shfl_xor_sync(0xffffffffu, rs1, 1);
        rs1 += __shfl_xor_sync(0xffffffffu, rs1, 2);
        l0 = l0*al0 + rs0; l1 = l1*al1 + rs1;
#pragma unroll
        for (int i = 0; i < 16; i++) {
            oacc[i][0]*=al0; oacc[i][1]*=al0; oacc[i][2]*=al1; oacc[i][3]*=al1;
        }

        __syncthreads();
        if (j < qb) {
            load_tile(Khs, qkvh, rowKV + (long long)(j+1)*128, colK);
        }
        cp_commit();

        uint32_t ph[16][2];
#pragma unroll
        for (int i = 0; i < 16; i++) {
            ph[i][0] = pack2h(__float2half(sacc[i][0]), __float2half(sacc[i][1]));
            ph[i][1] = pack2h(__float2half(sacc[i][2]), __float2half(sacc[i][3]));
        }

        cp_wait<1>();
        __syncthreads();

#pragma unroll
        for (int kk = 0; kk < 8; kk++) {
            uint32_t pa0 = ph[2*kk][0], pa1 = ph[2*kk][1], pa2 = ph[2*kk+1][0], pa3 = ph[2*kk+1][1];
            int vrow = kk*16 + vr8;
#pragma unroll
            for (int nn = 0; nn < 8; nn++) {
                int ch = nn*2 + vc;
                uint32_t r0,r1,r2,r3;
                ldsm_x4_t(r0,r1,r2,r3, Vhs + swz256(vrow, ch));
                mma16816(oacc[2*nn],   pa0,pa1,pa2,pa3, r0, r2);
                mma16816(oacc[2*nn+1], pa0,pa1,pa2,pa3, r1, r3);
            }
        }

        __syncthreads();
        if (j < qb) {
            load_tile(Vhs, qkvh, rowKV + (long long)(j+1)*128, colV);
        }
        cp_commit();
    }

    float i0 = 1.0f / l0, i1 = 1.0f / l1;
    long long r0w = (rowQ0 + wr + g) * DMODEL;
    long long r1w = r0w + 8LL * DMODEL;
#pragma unroll
    for (int i = 0; i < 16; i++) {
        int col = h * DHEAD + i*8 + 2*t;
        float v0 = oacc[i][0]*i0, v1 = oacc[i][1]*i0;
        float v2 = oacc[i][2]*i1, v3 = oacc[i][3]*i1;
        *(__half2*)(yh + r0w + col) = __halves2half2(__float2half(v0), __float2half(v1));
        *(__half2*)(yh + r1w + col) = __halves2half2(__float2half(v2), __float2half(v3));
    }
}

// ---------------------------------------------------------------------------
// Launch
// ---------------------------------------------------------------------------
extern "C" void kernel_launch(void* const* d_in, const int* in_sizes, int n_in,
                              void* d_out, int out_size)
{
    const float* x    = (const float*)d_in[0];
    const float* nw   = (const float*)d_in[1];
    const float* wqkv = (const float*)d_in[2];
    const float* wout = (const float*)d_in[3];
    float* out = (float*)d_out;

    fp16 *xnh, *wqh, *woh, *qh, *yh;
    cudaGetSymbolAddress((void**)&xnh, g_xn_hi);
    cudaGetSymbolAddress((void**)&wqh, g_wqkv_h);
    cudaGetSymbolAddress((void**)&woh, g_wout_h);
    cudaGetSymbolAddress((void**)&qh,  g_qkv_hi);
    cudaGetSymbolAddress((void**)&yh,  g_y_hi);

    const int GSMEM = 2 * 24576;   // 48KB double buffer
    const int FSMEM = 3 * 32768;   // 96KB
    cudaFuncSetAttribute((const void*)gemm_mma<true >, cudaFuncAttributeMaxDynamicSharedMemorySize, GSMEM);
    cudaFuncSetAttribute((const void*)gemm_mma<false>, cudaFuncAttributeMaxDynamicSharedMemorySize, GSMEM);
    cudaFuncSetAttribute((const void*)flash_attn, cudaFuncAttributeMaxDynamicSharedMemorySize, FSMEM);

    // 1) RMSNorm -> xn (fp16)
    rmsnorm_kernel<<<BROWS, 256>>>(x, nw, xnh);

    // 2) weight conversion (both matrices, one launch)
    {
        int n4a = QKVW * DMODEL / 4;
        int n4t = n4a + DMODEL * DMODEL / 4;
        convert_both<<<(n4t + 255) / 256, 256>>>(wqkv, wqh, n4a, wout, woh, n4t);
    }

    // 3) qkv = xn @ w_qkv^T  (plain fp16)
    gemm_mma<true><<<dim3(QKVW/64, BROWS/128), 256, GSMEM>>>(
        xnh, DMODEL,
        wqh, DMODEL,
        nullptr, qh, QKVW,
        DMODEL);

    // 4) fused flash attention -> y (merged heads)
    flash_attn<<<dim3(TSEQ/128, NBH), 256, FSMEM>>>(qh, yh);

    // 5) out = y @ w_out^T  (fp32 to d_out)
    gemm_mma<false><<<dim3(DMODEL/64, BROWS/128), 256, GSMEM>>>(
        yh, DMODEL,
        woh, DMODEL,
        out, nullptr, DMODEL,
        DMODEL);
}

// round 17
// speedup vs baseline: 1.5707x; 1.5707x over previous
#include <cuda_runtime.h>
#include <cuda_fp16.h>
#include <cstdint>

// Problem constants
#define TSEQ   2048
#define DMODEL 2048
#define NHEADS 16
#define DHEAD  128
#define BATCH  2
#define BROWS  (BATCH * TSEQ)      // 4096
#define QKVW   (3 * DMODEL)        // 6144
#define NBH    (BATCH * NHEADS)    // 32

typedef __half fp16;

// ---------------------------------------------------------------------------
// Scratch
// ---------------------------------------------------------------------------
__device__ fp16  g_xn_hi [(long long)BROWS * DMODEL];
__device__ fp16  g_wqkv_h[(long long)QKVW * DMODEL];
__device__ fp16  g_wout_h[(long long)DMODEL * DMODEL];
__device__ fp16  g_qkv_hi[(long long)BROWS * QKVW];
__device__ fp16  g_y_hi  [(long long)BROWS * DMODEL];

// ---------------------------------------------------------------------------
// helpers
// ---------------------------------------------------------------------------
__device__ __forceinline__ uint32_t pack2h(fp16 a, fp16 b) {
    __half2 p = __halves2half2(a, b);
    return *(uint32_t*)&p;
}
__device__ __forceinline__ float warpSum(float v) {
#pragma unroll
    for (int o = 16; o; o >>= 1) v += __shfl_xor_sync(0xffffffffu, v, o);
    return v;
}

// ---------------------------------------------------------------------------
// RMSNorm -> fp16
// ---------------------------------------------------------------------------
__global__ __launch_bounds__(256) void rmsnorm_kernel(
    const float* __restrict__ x, const float* __restrict__ w,
    fp16* __restrict__ xh)
{
    long long base = (long long)blockIdx.x * DMODEL;
    int tid = threadIdx.x;
    const float4* xr = (const float4*)(x + base);
    float4 v0 = xr[tid];
    float4 v1 = xr[tid + 256];
    float s = v0.x*v0.x + v0.y*v0.y + v0.z*v0.z + v0.w*v0.w
            + v1.x*v1.x + v1.y*v1.y + v1.z*v1.z + v1.w*v1.w;

    __shared__ float sh[8];
    s = warpSum(s);
    if ((tid & 31) == 0) sh[tid >> 5] = s;
    __syncthreads();
    float tot = 0.f;
#pragma unroll
    for (int i = 0; i < 8; i++) tot += sh[i];
    float r = rsqrtf(tot / (float)DMODEL + 1e-6f);

    const float4* wr = (const float4*)w;
    float4 w0 = wr[tid], w1 = wr[tid + 256];
    float4 o0, o1;
    o0.x = v0.x*r*w0.x; o0.y = v0.y*r*w0.y; o0.z = v0.z*r*w0.z; o0.w = v0.w*r*w0.w;
    o1.x = v1.x*r*w1.x; o1.y = v1.y*r*w1.y; o1.z = v1.z*r*w1.z; o1.w = v1.w*r*w1.w;
    fp16* d0 = xh + base + tid*4;
    *(__half2*)(d0)     = __halves2half2(__float2half(o0.x), __float2half(o0.y));
    *(__half2*)(d0 + 2) = __halves2half2(__float2half(o0.z), __float2half(o0.w));
    fp16* d1 = xh + base + 1024 + tid*4;
    *(__half2*)(d1)     = __halves2half2(__float2half(o1.x), __float2half(o1.y));
    *(__half2*)(d1 + 2) = __halves2half2(__float2half(o1.z), __float2half(o1.w));
}

// ---------------------------------------------------------------------------
// fp32 -> fp16 conversion for BOTH weight matrices in one launch.
// ---------------------------------------------------------------------------
__global__ __launch_bounds__(256) void convert_both(
    const float* __restrict__ srcA, fp16* __restrict__ dstA, int n4a,
    const float* __restrict__ srcB, fp16* __restrict__ dstB, int n4total)
{
    int i = blockIdx.x * 256 + threadIdx.x;
    if (i < n4total) {
        const float* s; fp16* d; int k;
        if (i < n4a) { s = srcA; d = dstA; k = i; }
        else         { s = srcB; d = dstB; k = i - n4a; }
        float4 v = ((const float4*)s)[k];
        fp16* o = d + (long long)k*4;
        *(__half2*)(o)     = __halves2half2(__float2half(v.x), __float2half(v.y));
        *(__half2*)(o + 2) = __halves2half2(__float2half(v.z), __float2half(v.w));
    }
}

// ---------------------------------------------------------------------------
// mma.sync primitives (fp16)
// ---------------------------------------------------------------------------
__device__ __forceinline__ void ldsm_x4(uint32_t& r0, uint32_t& r1, uint32_t& r2, uint32_t& r3, uint32_t addr) {
    asm volatile("ldmatrix.sync.aligned.m8n8.x4.shared.b16 {%0,%1,%2,%3}, [%4];"
        : "=r"(r0), "=r"(r1), "=r"(r2), "=r"(r3) : "r"(addr));
}
__device__ __forceinline__ void ldsm_x4_t(uint32_t& r0, uint32_t& r1, uint32_t& r2, uint32_t& r3, uint32_t addr) {
    asm volatile("ldmatrix.sync.aligned.m8n8.x4.trans.shared.b16 {%0,%1,%2,%3}, [%4];"
        : "=r"(r0), "=r"(r1), "=r"(r2), "=r"(r3) : "r"(addr));
}
__device__ __forceinline__ void mma16816(float* d, uint32_t a0, uint32_t a1, uint32_t a2, uint32_t a3,
                                         uint32_t b0, uint32_t b1) {
    asm volatile("mma.sync.aligned.m16n8k16.row.col.f32.f16.f16.f32 "
        "{%0,%1,%2,%3}, {%4,%5,%6,%7}, {%8,%9}, {%0,%1,%2,%3};"
        : "+f"(d[0]), "+f"(d[1]), "+f"(d[2]), "+f"(d[3])
        : "r"(a0), "r"(a1), "r"(a2), "r"(a3), "r"(b0), "r"(b1));
}
__device__ __forceinline__ void cp16(uint32_t dst, const void* src) {
    asm volatile("cp.async.cg.shared.global [%0], [%1], 16;" :: "r"(dst), "l"(src));
}
__device__ __forceinline__ void cp_commit() {
    asm volatile("cp.async.commit_group;" ::: "memory");
}
template<int N>
__device__ __forceinline__ void cp_wait() {
    asm volatile("cp.async.wait_group %0;" :: "n"(N) : "memory");
}
__device__ __forceinline__ uint32_t smem_u32(const void* p) {
    uint32_t a;
    asm("{ .reg .u64 t; cvta.to.shared.u64 t, %1; cvt.u32.u64 %0, t; }" : "=r"(a) : "l"(p));
    return a;
}
// swizzled addr inside a [rows x 128 halves] tile (256B rows, 16 x 16B chunks)
__device__ __forceinline__ uint32_t swz256(int row, int ch) {
    return (uint32_t)(row * 256 + ((ch ^ (row & 7)) * 16));
}
// swizzled addr inside a [rows x 64 halves] tile (128B rows, 8 x 16B chunks)
__device__ __forceinline__ uint32_t sw_off(int row, int c16) {
    return (uint32_t)(row * 128 + ((c16 ^ (row & 7)) * 16));
}

// ---------------------------------------------------------------------------
// Plain fp16 GEMM, narrow tile for 3-CTA/SM occupancy. (R13, unchanged)
// C[M,N] = A[M,K] * B[N,K]^T. CTA tile 128x64, BK=64, 256 threads,
// 8 warps as 4x2 grid (warp tile 32x32).
// ---------------------------------------------------------------------------
template<bool EPI_HALF>
__global__ __launch_bounds__(256, 3) void gemm_mma(
    const fp16* __restrict__ Ahi, int lda,
    const fp16* __restrict__ Bh, int ldb,
    float* __restrict__ Cf, fp16* __restrict__ Chi, int ldc,
    int K)
{
    const int STAGE = 24576;          // A 16KB + B 8KB
    const int OFF_B = 16384;
    int bm = blockIdx.y, bn = blockIdx.x;

    extern __shared__ char smem[];
    uint32_t sbase = smem_u32(smem);

    int tid = threadIdx.x;
    int wid = tid >> 5, lane = tid & 31;
    int wm = wid >> 1, wn = wid & 1;   // 4 x 2 warp grid: 32 rows x 32 cols per warp

    const fp16* Abase = Ahi + (long long)bm * 128 * lda;
    const fp16* Bbase = Bh  + (long long)bn * 64 * ldb;

    int nIter = K >> 6;

    int lrow = tid >> 3;          // 0..31
    int lseg = tid & 7;           // 16B chunk within 128B row

    auto load_chunk = [&](int kc, int bufsel) {
        int k0 = kc << 6;
        uint32_t st = sbase + bufsel * STAGE;
#pragma unroll
        for (int i = 0; i < 4; i++) {
            int row = lrow + 32 * i;
            cp16(st + sw_off(row, lseg), Abase + (long long)row * lda + k0 + lseg * 8);
        }
#pragma unroll
        for (int i = 0; i < 2; i++) {
            int row = lrow + 32 * i;
            cp16(st + OFF_B + sw_off(row, lseg), Bbase + (long long)row * ldb + k0 + lseg * 8);
        }
        cp_commit();
    };

    float acc[2][4][4];
#pragma unroll
    for (int a = 0; a < 2; a++)
#pragma unroll
        for (int b = 0; b < 4; b++)
#pragma unroll
            for (int c = 0; c < 4; c++) acc[a][b][c] = 0.f;

    int lr8  = (lane & 7) + ((lane >> 3) & 1) * 8;
    int lk16 = (lane >> 4);

    load_chunk(0, 0);

    for (int it = 0; it < nIter; ++it) {
        if (it + 1 < nIter) {
            load_chunk(it + 1, (it + 1) & 1);
            cp_wait<1>();
        } else {
            cp_wait<0>();
        }
        __syncthreads();

        uint32_t As  = sbase + (it & 1) * STAGE;
        uint32_t Bs  = As + OFF_B;
#pragma unroll
        for (int ks = 0; ks < 4; ks++) {
            int c16 = ks * 2 + lk16;
            uint32_t bfr[2][4];
#pragma unroll
            for (int ni = 0; ni < 2; ni++) {
                int row = wn * 32 + ni * 16 + lr8;
                ldsm_x4(bfr[ni][0], bfr[ni][1], bfr[ni][2], bfr[ni][3], Bs + sw_off(row, c16));
            }
            uint32_t ah[2][4];
#pragma unroll
            for (int mi = 0; mi < 2; mi++) {
                int row = wm * 32 + mi * 16 + lr8;
                ldsm_x4(ah[mi][0], ah[mi][1], ah[mi][2], ah[mi][3], As + sw_off(row, c16));
            }
#pragma unroll
            for (int mi = 0; mi < 2; mi++) {
#pragma unroll
                for (int ni = 0; ni < 2; ni++) {
                    mma16816(acc[mi][ni*2+0], ah[mi][0], ah[mi][1], ah[mi][2], ah[mi][3],
                             bfr[ni][0], bfr[ni][2]);
                    mma16816(acc[mi][ni*2+1], ah[mi][0], ah[mi][1], ah[mi][2], ah[mi][3],
                             bfr[ni][1], bfr[ni][3]);
                }
            }
        }
        __syncthreads();
    }

    int g = lane >> 2, t = lane & 3;
    long long Cbase = (long long)bm * 128 * ldc + (long long)bn * 64;
#pragma unroll
    for (int mi = 0; mi < 2; mi++) {
#pragma unroll
        for (int nc = 0; nc < 4; nc++) {
            int m0 = wm * 32 + mi * 16 + g;
            int n0 = wn * 32 + nc * 8 + t * 2;
            float v0 = acc[mi][nc][0];
            float v1 = acc[mi][nc][1];
            float v2 = acc[mi][nc][2];
            float v3 = acc[mi][nc][3];
            if (EPI_HALF) {
                *(__half2*)(Chi + Cbase + (long long)m0*ldc + n0) =
                    __halves2half2(__float2half(v0), __float2half(v1));
                *(__half2*)(Chi + Cbase + (long long)(m0+8)*ldc + n0) =
                    __halves2half2(__float2half(v2), __float2half(v3));
            } else {
                *(float2*)(Cf + Cbase + (long long)m0*ldc + n0)     = make_float2(v0, v1);
                *(float2*)(Cf + Cbase + (long long)(m0+8)*ldc + n0) = make_float2(v2, v3);
            }
        }
    }
}

// ---------------------------------------------------------------------------
// Fused flash attention (causal), plain fp16.
// 64 q-rows per CTA, 128 threads (4 warps x 16 rows), 2 CTAs/SM.
// smem: Q 16KB + K 32KB + V 32KB = 80KB.
// ---------------------------------------------------------------------------
__global__ __launch_bounds__(128, 2) void flash_attn(
    const fp16* __restrict__ qkvh, fp16* __restrict__ yh)
{
    extern __shared__ char smem[];
    uint32_t sb = smem_u32(smem);
    const uint32_t Qhs = sb;
    const uint32_t Khs = sb + 16384;
    const uint32_t Vhs = sb + 49152;

    int tid = threadIdx.x, lane = tid & 31, wid = tid >> 5;
    int qb = (int)(gridDim.x - 1) - (int)blockIdx.x;    // 0..31, heavy first
    int z = blockIdx.y; int b = z >> 4, h = z & 15;
    long long rowQ0 = (long long)b * TSEQ + (long long)qb * 64;
    long long rowKV = (long long)b * TSEQ;
    int colQ = h * DHEAD, colK = DMODEL + h * DHEAD, colV = 2*DMODEL + h * DHEAD;

    auto load_kv = [&](uint32_t dst, long long grow0, int col0) {
#pragma unroll
        for (int i = 0; i < 16; i++) {
            int lin = tid + 128 * i;
            int row = lin >> 4, ch = lin & 15;
            cp16(dst + swz256(row, ch), qkvh + (grow0 + row) * QKVW + col0 + ch * 8);
        }
    };
    {
#pragma unroll
        for (int i = 0; i < 8; i++) {
            int lin = tid + 128 * i;
            int row = lin >> 4, ch = lin & 15;
            cp16(Qhs + swz256(row, ch), qkvh + (rowQ0 + row) * QKVW + colQ + ch * 8);
        }
    }
    load_kv(Khs, rowKV, colK);
    cp_commit();
    load_kv(Vhs, rowKV, colV);
    cp_commit();

    int nj = (qb * 64 + 63) / 128 + 1;   // number of 128-key tiles

    float sacc[16][4];
    float oacc[16][4];
#pragma unroll
    for (int i=0;i<16;i++) { oacc[i][0]=0.f; oacc[i][1]=0.f; oacc[i][2]=0.f; oacc[i][3]=0.f; }
    float m0 = -1e30f, m1 = -1e30f, l0 = 0.f, l1 = 0.f;

    int g = lane >> 2, t = lane & 3;
    int wr = wid * 16;
    int lr8  = (lane & 7) + ((lane >> 3) & 1) * 8;
    int lk16 = lane >> 4;
    int vr8  = (lane & 7) + ((lane >> 4) & 1) * 8;
    int vc   = (lane >> 3) & 1;

    const float sm_scale = 0.08838834764831845f;
    int q0row = qb * 64 + wr + g;
    int q1row = q0row + 8;

    for (int j = 0; j < nj; ++j) {
        cp_wait<1>();
        __syncthreads();

#pragma unroll
        for (int i=0;i<16;i++) { sacc[i][0]=0.f; sacc[i][1]=0.f; sacc[i][2]=0.f; sacc[i][3]=0.f; }
#pragma unroll
        for (int c = 0; c < 8; c++) {
            int ch = 2*c + lk16;
            int arow = wr + lr8;
            uint32_t ah0,ah1,ah2,ah3;
            ldsm_x4(ah0,ah1,ah2,ah3, Qhs + swz256(arow, ch));
#pragma unroll
            for (int nn = 0; nn < 8; nn++) {
                uint32_t r0,r1,r2,r3;
                ldsm_x4(r0,r1,r2,r3, Khs + swz256(nn*16 + lr8, ch));
                mma16816(sacc[2*nn],   ah0,ah1,ah2,ah3, r0, r2);
                mma16816(sacc[2*nn+1], ah0,ah1,ah2,ah3, r1, r3);
            }
        }

        float nm0 = -1e30f, nm1 = -1e30f;
        bool diag = (j == nj - 1);
#pragma unroll
        for (int i = 0; i < 16; i++) {
            int kc = j*128 + i*8 + 2*t;
            float s0 = sacc[i][0]*sm_scale, s1 = sacc[i][1]*sm_scale;
            float s2 = sacc[i][2]*sm_scale, s3 = sacc[i][3]*sm_scale;
            if (diag) {
                if (kc     > q0row) s0 = -1e30f;
                if (kc + 1 > q0row) s1 = -1e30f;
                if (kc     > q1row) s2 = -1e30f;
                if (kc + 1 > q1row) s3 = -1e30f;
            }
            sacc[i][0]=s0; sacc[i][1]=s1; sacc[i][2]=s2; sacc[i][3]=s3;
            nm0 = fmaxf(nm0, fmaxf(s0, s1));
            nm1 = fmaxf(nm1, fmaxf(s2, s3));
        }
        nm0 = fmaxf(nm0, __shfl_xor_sync(0xffffffffu, nm0, 1));
        nm0 = fmaxf(nm0, __shfl_xor_sync(0xffffffffu, nm0, 2));
        nm1 = fmaxf(nm1, __shfl_xor_sync(0xffffffffu, nm1, 1));
        nm1 = fmaxf(nm1, __shfl_xor_sync(0xffffffffu, nm1, 2));
        nm0 = fmaxf(m0, nm0); nm1 = fmaxf(m1, nm1);
        float al0 = __expf(m0 - nm0), al1 = __expf(m1 - nm1);
        m0 = nm0; m1 = nm1;

        float rs0 = 0.f, rs1 = 0.f;
#pragma unroll
        for (int i = 0; i < 16; i++) {
            float e0 = __expf(sacc[i][0] - nm0);
            float e1 = __expf(sacc[i][1] - nm0);
            float e2 = __expf(sacc[i][2] - nm1);
            float e3 = __expf(sacc[i][3] - nm1);
            rs0 += e0 + e1; rs1 += e2 + e3;
            sacc[i][0]=e0; sacc[i][1]=e1; sacc[i][2]=e2; sacc[i][3]=e3;
        }
        rs0 += __shfl_xor_sync(0xffffffffu, rs0, 1);
        rs0 += __shfl_xor_sync(0xffffffffu, rs0, 2);
        rs1 += __shfl_xor_sync(0xffffffffu, rs1, 1);
        rs1 += __shfl_xor_sync(0xffffffffu, rs1, 2);
        l0 = l0*al0 + rs0; l1 = l1*al1 + rs1;
#pragma unroll
        for (int i = 0; i < 16; i++) {
            oacc[i][0]*=al0; oacc[i][1]*=al0; oacc[i][2]*=al1; oacc[i][3]*=al1;
        }

        __syncthreads();
        if (j + 1 < nj) {
            load_kv(Khs, rowKV + (long long)(j+1)*128, colK);
        }
        cp_commit();

        uint32_t ph[16][2];
#pragma unroll
        for (int i = 0; i < 16; i++) {
            ph[i][0] = pack2h(__float2half(sacc[i][0]), __float2half(sacc[i][1]));
            ph[i][1] = pack2h(__float2half(sacc[i][2]), __float2half(sacc[i][3]));
        }

        cp_wait<1>();
        __syncthreads();

#pragma unroll
        for (int kk = 0; kk < 8; kk++) {
            uint32_t pa0 = ph[2*kk][0], pa1 = ph[2*kk][1], pa2 = ph[2*kk+1][0], pa3 = ph[2*kk+1][1];
            int vrow = kk*16 + vr8;
#pragma unroll
            for (int nn = 0; nn < 8; nn++) {
                int ch = nn*2 + vc;
                uint32_t r0,r1,r2,r3;
                ldsm_x4_t(r0,r1,r2,r3, Vhs + swz256(vrow, ch));
                mma16816(oacc[2*nn],   pa0,pa1,pa2,pa3, r0, r2);
                mma16816(oacc[2*nn+1], pa0,pa1,pa2,pa3, r1, r3);
            }
        }

        __syncthreads();
        if (j + 1 < nj) {
            load_kv(Vhs, rowKV + (long long)(j+1)*128, colV);
        }
        cp_commit();
    }

    float i0 = 1.0f / l0, i1 = 1.0f / l1;
    long long r0w = (rowQ0 + wr + g) * DMODEL;
    long long r1w = r0w + 8LL * DMODEL;
#pragma unroll
    for (int i = 0; i < 16; i++) {
        int col = h * DHEAD + i*8 + 2*t;
        float v0 = oacc[i][0]*i0, v1 = oacc[i][1]*i0;
        float v2 = oacc[i][2]*i1, v3 = oacc[i][3]*i1;
        *(__half2*)(yh + r0w + col) = __halves2half2(__float2half(v0), __float2half(v1));
        *(__half2*)(yh + r1w + col) = __halves2half2(__float2half(v2), __float2half(v3));
    }
}

// ---------------------------------------------------------------------------
// Launch
// ---------------------------------------------------------------------------
extern "C" void kernel_launch(void* const* d_in, const int* in_sizes, int n_in,
                              void* d_out, int out_size)
{
    const float* x    = (const float*)d_in[0];
    const float* nw   = (const float*)d_in[1];
    const float* wqkv = (const float*)d_in[2];
    const float* wout = (const float*)d_in[3];
    float* out = (float*)d_out;

    fp16 *xnh, *wqh, *woh, *qh, *yh;
    cudaGetSymbolAddress((void**)&xnh, g_xn_hi);
    cudaGetSymbolAddress((void**)&wqh, g_wqkv_h);
    cudaGetSymbolAddress((void**)&woh, g_wout_h);
    cudaGetSymbolAddress((void**)&qh,  g_qkv_hi);
    cudaGetSymbolAddress((void**)&yh,  g_y_hi);

    const int GSMEM = 2 * 24576;   // 48KB double buffer
    const int FSMEM = 81920;       // 80KB (Q 16K + K 32K + V 32K)
    cudaFuncSetAttribute((const void*)gemm_mma<true >, cudaFuncAttributeMaxDynamicSharedMemorySize, GSMEM);
    cudaFuncSetAttribute((const void*)gemm_mma<false>, cudaFuncAttributeMaxDynamicSharedMemorySize, GSMEM);
    cudaFuncSetAttribute((const void*)flash_attn, cudaFuncAttributeMaxDynamicSharedMemorySize, FSMEM);

    // 1) RMSNorm -> xn (fp16)
    rmsnorm_kernel<<<BROWS, 256>>>(x, nw, xnh);

    // 2) weight conversion (both matrices, one launch)
    {
        int n4a = QKVW * DMODEL / 4;
        int n4t = n4a + DMODEL * DMODEL / 4;
        convert_both<<<(n4t + 255) / 256, 256>>>(wqkv, wqh, n4a, wout, woh, n4t);
    }

    // 3) qkv = xn @ w_qkv^T  (plain fp16)
    gemm_mma<true><<<dim3(QKVW/64, BROWS/128), 256, GSMEM>>>(
        xnh, DMODEL,
        wqh, DMODEL,
        nullptr, qh, QKVW,
        DMODEL);

    // 4) fused flash attention -> y (merged heads), 64-row q-blocks, 2 CTAs/SM
    flash_attn<<<dim3(TSEQ/64, NBH), 128, FSMEM>>>(qh, yh);

    // 5) out = y @ w_out^T  (fp32 to d_out)
    gemm_mma<false><<<dim3(DMODEL/64, BROWS/128), 256, GSMEM>>>(
        yh, DMODEL,
        woh, DMODEL,
        out, nullptr, DMODEL,
        DMODEL);
}